// round 2
// baseline (speedup 1.0000x reference)
#include <cuda_runtime.h>

#define BB 2
#define NN 384
#define DD 768
#define EE 64
#define HH 512

// -------- scratch (no allocations allowed) --------
__device__ float g_agg[BB * NN * EE];     //  192 KB
__device__ float g_NI [BB * NN * HH];     // 1.5 MB  (nodes@Wi + eb1)
__device__ float g_NJ [BB * NN * HH];     // 1.5 MB  (nodes@Wj)

// ============================================================
// Kernel 1: agg[b,i,e] = sum_j edges[b,i,j,e] * adj[b,i,j]
// grid = BB*NN blocks, 256 threads. 90% of adj is zero -> skip.
// ============================================================
__global__ __launch_bounds__(256) void k_agg(const float* __restrict__ edges,
                                             const float* __restrict__ adj)
{
    int bi = blockIdx.x;                 // b*NN + i
    int e  = threadIdx.x & 63;
    int jg = threadIdx.x >> 6;           // 0..3
    const float* erow = edges + (size_t)bi * NN * EE;
    const float* arow = adj   + (size_t)bi * NN;
    float acc = 0.f;
    for (int j = jg; j < NN; j += 4) {
        float a = arow[j];               // warp-uniform (all 32 lanes same j? lanes share jg, e spans 32 -> j uniform)
        if (a != 0.f) acc += erow[(size_t)j * EE + e] * a;
    }
    __shared__ float red[4][64];
    red[jg][e] = acc;
    __syncthreads();
    if (jg == 0)
        g_agg[(size_t)bi * EE + e] = red[0][e] + red[1][e] + red[2][e] + red[3][e];
}

// ============================================================
// Kernel 2: NI = nodes @ Wi + eb1 ; NJ = nodes @ Wj
//   Wi = ew1[64 : 64+768], Wj = ew1[832 : 1600]   (rows of ew1)
// grid = (2 col-halves, 48 row-tiles of 16, 2 {NI,NJ}), 256 thr
// ============================================================
__global__ __launch_bounds__(256) void k_ninj(const float* __restrict__ nodes,
                                              const float* __restrict__ ew1,
                                              const float* __restrict__ eb1)
{
    __shared__ float sA[16 * DD];        // 48 KB: 16 node rows
    const int tid   = threadIdx.x;
    const int cbase = blockIdx.x * 256;
    const int r0    = blockIdx.y * 16;   // global flattened row (b*NN+i)
    const int z     = blockIdx.z;        // 0 = NI, 1 = NJ
    const int rg    = tid >> 6;          // 0..3 -> 4 rows each
    const int cc    = tid & 63;          // -> 4 cols each

    // stage A tile (coalesced, flat copy)
    #pragma unroll
    for (int t = 0; t < 48; t++) {
        int lin = t * 256 + tid;         // 16*768 = 12288
        sA[lin] = nodes[(size_t)r0 * DD + lin];
    }
    __syncthreads();

    const int woff = 64 + z * DD;        // row offset into ew1
    float acc[4][4];
    #pragma unroll
    for (int q = 0; q < 4; q++)
        #pragma unroll
        for (int x = 0; x < 4; x++) acc[q][x] = 0.f;

    #pragma unroll 4
    for (int k = 0; k < DD; k++) {
        float4 w = __ldg((const float4*)&ew1[(size_t)(woff + k) * HH + cbase + cc * 4]);
        #pragma unroll
        for (int q = 0; q < 4; q++) {
            float a = sA[(rg * 4 + q) * DD + k];   // broadcast within warp
            acc[q][0] += a * w.x; acc[q][1] += a * w.y;
            acc[q][2] += a * w.z; acc[q][3] += a * w.w;
        }
    }

    float* dst = (z == 0) ? g_NI : g_NJ;
    float4 bb = make_float4(0.f, 0.f, 0.f, 0.f);
    if (z == 0) bb = __ldg((const float4*)&eb1[cbase + cc * 4]);
    #pragma unroll
    for (int q = 0; q < 4; q++) {
        int g = r0 + rg * 4 + q;
        float4 o = make_float4(acc[q][0] + bb.x, acc[q][1] + bb.y,
                               acc[q][2] + bb.z, acc[q][3] + bb.w);
        *(float4*)&dst[(size_t)g * HH + cbase + cc * 4] = o;
    }
}

// ============================================================
// Kernel 3: node path. 8 rows per block, 96 blocks, 256 thr.
//  msg = [agg | nodes*384]; pre = msg@nw1+nb1; h = LN*ng+nbt;
//  out = nodes + relu(h)@nw2 + nb2
// ============================================================
#define MK (EE + DD)   /* 832 */
__global__ __launch_bounds__(256) void k_node(const float* __restrict__ nodes,
                                              const float* __restrict__ nw1,
                                              const float* __restrict__ nb1,
                                              const float* __restrict__ ng,
                                              const float* __restrict__ nbt,
                                              const float* __restrict__ nw2,
                                              const float* __restrict__ nb2,
                                              float* __restrict__ out_nodes)
{
    __shared__ float sM[8 * MK];         // 26.6 KB
    __shared__ float sH[8 * 516];        // 16.5 KB (padded stride)
    const int tid = threadIdx.x;
    const int r0  = blockIdx.x * 8;

    // stage messages
    for (int t = 0; t < 26; t++) {
        int lin = t * 256 + tid;         // 8*832 = 6656 exactly
        int r = lin / MK, c = lin - r * MK;
        int g = r0 + r;
        float v = (c < EE) ? g_agg[(size_t)g * EE + c]
                           : nodes[(size_t)g * DD + (c - EE)] * (float)NN;
        sM[lin] = v;
    }
    __syncthreads();

    // phase 1: pre[8][512]
    const int rg = tid >> 7;             // 0..1 -> rows rg*4..+3
    const int hc = tid & 127;            // -> cols hc*4..+3
    float acc[4][4];
    #pragma unroll
    for (int q = 0; q < 4; q++)
        #pragma unroll
        for (int x = 0; x < 4; x++) acc[q][x] = 0.f;

    #pragma unroll 4
    for (int k = 0; k < MK; k++) {
        float4 w = __ldg((const float4*)&nw1[(size_t)k * HH + hc * 4]);
        #pragma unroll
        for (int q = 0; q < 4; q++) {
            float a = sM[(rg * 4 + q) * MK + k];
            acc[q][0] += a * w.x; acc[q][1] += a * w.y;
            acc[q][2] += a * w.z; acc[q][3] += a * w.w;
        }
    }
    {
        float4 b4 = __ldg((const float4*)&nb1[hc * 4]);
        #pragma unroll
        for (int q = 0; q < 4; q++) {
            float* d = &sH[(rg * 4 + q) * 516 + hc * 4];
            *(float4*)d = make_float4(acc[q][0] + b4.x, acc[q][1] + b4.y,
                                      acc[q][2] + b4.z, acc[q][3] + b4.w);
        }
    }
    __syncthreads();

    // LN + relu: warp w handles row w
    {
        int wid = tid >> 5, lane = tid & 31;
        float s = 0.f, ss = 0.f;
        #pragma unroll
        for (int m = 0; m < 16; m++) {
            float v = sH[wid * 516 + lane + m * 32];
            s += v; ss += v * v;
        }
        #pragma unroll
        for (int m = 16; m >= 1; m >>= 1) {
            s  += __shfl_xor_sync(0xffffffffu, s, m);
            ss += __shfl_xor_sync(0xffffffffu, ss, m);
        }
        float mu = s * (1.f / HH);
        float var = ss * (1.f / HH) - mu * mu;
        float rs = rsqrtf(var + 1e-5f);
        #pragma unroll
        for (int m = 0; m < 16; m++) {
            int h = lane + m * 32;
            float v = sH[wid * 516 + h];
            v = (v - mu) * rs * __ldg(&ng[h]) + __ldg(&nbt[h]);
            sH[wid * 516 + h] = fmaxf(v, 0.f);
        }
    }
    __syncthreads();

    // phase 2: out = nodes + relu_h @ nw2 + nb2
    float acc2[8][3];
    #pragma unroll
    for (int r = 0; r < 8; r++)
        #pragma unroll
        for (int k = 0; k < 3; k++) acc2[r][k] = 0.f;

    #pragma unroll 2
    for (int h = 0; h < HH; h++) {
        float w0 = __ldg(&nw2[(size_t)h * DD + tid]);
        float w1 = __ldg(&nw2[(size_t)h * DD + tid + 256]);
        float w2 = __ldg(&nw2[(size_t)h * DD + tid + 512]);
        #pragma unroll
        for (int r = 0; r < 8; r++) {
            float a = sH[r * 516 + h];
            acc2[r][0] += a * w0; acc2[r][1] += a * w1; acc2[r][2] += a * w2;
        }
    }
    #pragma unroll
    for (int r = 0; r < 8; r++) {
        int g = r0 + r;
        #pragma unroll
        for (int k = 0; k < 3; k++) {
            int d = tid + k * 256;
            out_nodes[(size_t)g * DD + d] =
                __ldg(&nodes[(size_t)g * DD + d]) + acc2[r][k] + __ldg(&nb2[d]);
        }
    }
}

// ============================================================
// Kernel 4: fused edge path.  Block = one (b,i) x 64-j tile.
//  he = E@We + NI[i] + NJ[j] (+eb1 folded into NI)
//  he = relu(LN(he)*eg+ebt);  out = edges + he@ew2 + eb2
// smem: sE[64][64] | sW[64][128] (reused [128][64]) | sHe[64][516]
// ============================================================
#define SHE_STRIDE 516
#define EDGE_SMEM ((64*64 + 64*128 + 64*SHE_STRIDE + 128) * 4)

__global__ __launch_bounds__(256, 1) void k_edge(
    const float* __restrict__ edges,
    const float* __restrict__ ew1,   // We = first 64 rows
    const float* __restrict__ eg,
    const float* __restrict__ ebt,
    const float* __restrict__ ew2,
    const float* __restrict__ eb2,
    float* __restrict__ out_edges)
{
    extern __shared__ float smem[];
    float* sE   = smem;                       // [64][64]
    float* sW   = sE + 64 * 64;               // [64][128] / [128][64]
    float* sHe  = sW + 64 * 128;              // [64][516]
    float* sMu  = sHe + 64 * SHE_STRIDE;      // [64]
    float* sRst = sMu + 64;                   // [64]

    const int tid = threadIdx.x;
    const int b = blockIdx.z, i = blockIdx.y, jt = blockIdx.x;
    const int j0 = jt * 64;
    const int rg = tid >> 4;                  // 0..15 -> rows rg*4..+3
    const int hc = tid & 15;

    // stage edge tile (kept resident for the final residual)
    const float* etile = edges + ((size_t)((size_t)b * NN + i) * NN + j0) * EE;
    #pragma unroll
    for (int t = 0; t < 16; t++) {
        int lin = t * 256 + tid;
        sE[lin] = etile[lin];
    }

    float rsum[4] = {0.f, 0.f, 0.f, 0.f}, rsq[4] = {0.f, 0.f, 0.f, 0.f};
    const float* nip_base = g_NI + (size_t)((size_t)b * NN + i) * HH;

    // ---------------- GEMM1 in 4 h-chunks of 128 ----------------
    for (int c = 0; c < 4; c++) {
        const int hb = c * 128;
        __syncthreads();
        #pragma unroll
        for (int t = 0; t < 32; t++) {
            int lin = t * 256 + tid;          // 64*128
            int e = lin >> 7, hh = lin & 127;
            sW[lin] = ew1[(size_t)e * HH + hb + hh];
        }
        __syncthreads();

        float acc[4][8];
        #pragma unroll
        for (int q = 0; q < 4; q++)
            #pragma unroll
            for (int x = 0; x < 8; x++) acc[q][x] = 0.f;

        #pragma unroll 8
        for (int e = 0; e < 64; e++) {
            const float* wp = &sW[e * 128 + hc * 8];
            float4 w0 = *(const float4*)(wp);
            float4 w1 = *(const float4*)(wp + 4);
            #pragma unroll
            for (int q = 0; q < 4; q++) {
                float a = sE[(rg * 4 + q) * 64 + e];
                acc[q][0] += a * w0.x; acc[q][1] += a * w0.y;
                acc[q][2] += a * w0.z; acc[q][3] += a * w0.w;
                acc[q][4] += a * w1.x; acc[q][5] += a * w1.y;
                acc[q][6] += a * w1.z; acc[q][7] += a * w1.w;
            }
        }

        // epilogue: add NI + NJ, write sHe, accumulate row stats
        float4 ni0 = __ldg((const float4*)(nip_base + hb + hc * 8));
        float4 ni1 = __ldg((const float4*)(nip_base + hb + hc * 8 + 4));
        #pragma unroll
        for (int q = 0; q < 4; q++) {
            int j = j0 + rg * 4 + q;
            const float* njp = g_NJ + (size_t)((size_t)b * NN + j) * HH + hb + hc * 8;
            float4 nj0 = __ldg((const float4*)njp);
            float4 nj1 = __ldg((const float4*)(njp + 4));
            float v0 = acc[q][0] + ni0.x + nj0.x;
            float v1 = acc[q][1] + ni0.y + nj0.y;
            float v2 = acc[q][2] + ni0.z + nj0.z;
            float v3 = acc[q][3] + ni0.w + nj0.w;
            float v4 = acc[q][4] + ni1.x + nj1.x;
            float v5 = acc[q][5] + ni1.y + nj1.y;
            float v6 = acc[q][6] + ni1.z + nj1.z;
            float v7 = acc[q][7] + ni1.w + nj1.w;
            float* dst = &sHe[(rg * 4 + q) * SHE_STRIDE + hb + hc * 8];
            *(float4*)dst       = make_float4(v0, v1, v2, v3);
            *(float4*)(dst + 4) = make_float4(v4, v5, v6, v7);
            rsum[q] += v0 + v1 + v2 + v3 + v4 + v5 + v6 + v7;
            rsq[q]  += v0*v0 + v1*v1 + v2*v2 + v3*v3 + v4*v4 + v5*v5 + v6*v6 + v7*v7;
        }
    }

    // ---------------- row stats: reduce over 16 hc lanes ----------------
    #pragma unroll
    for (int q = 0; q < 4; q++) {
        float s = rsum[q], ss = rsq[q];
        #pragma unroll
        for (int m = 8; m >= 1; m >>= 1) {
            s  += __shfl_xor_sync(0xffffffffu, s, m);
            ss += __shfl_xor_sync(0xffffffffu, ss, m);
        }
        if (hc == 0) {
            float mu = s * (1.f / HH);
            float var = ss * (1.f / HH) - mu * mu;
            sMu[rg * 4 + q]  = mu;
            sRst[rg * 4 + q] = rsqrtf(var + 1e-5f);
        }
    }
    __syncthreads();

    // ---------------- normalize + relu (in place) ----------------
    #pragma unroll
    for (int t = 0; t < 32; t++) {
        int lin = t * 256 + tid;              // float4 index over [64][512]
        int r = lin >> 7, hq = lin & 127;
        float4 v = *(float4*)&sHe[r * SHE_STRIDE + hq * 4];
        float mu = sMu[r], rs = sRst[r];
        float4 g4 = __ldg((const float4*)&eg[hq * 4]);
        float4 b4 = __ldg((const float4*)&ebt[hq * 4]);
        v.x = fmaxf((v.x - mu) * rs * g4.x + b4.x, 0.f);
        v.y = fmaxf((v.y - mu) * rs * g4.y + b4.y, 0.f);
        v.z = fmaxf((v.z - mu) * rs * g4.z + b4.z, 0.f);
        v.w = fmaxf((v.w - mu) * rs * g4.w + b4.w, 0.f);
        *(float4*)&sHe[r * SHE_STRIDE + hq * 4] = v;
    }

    // ---------------- GEMM2 in 4 h-chunks of 128 ----------------
    float accE[4][4];
    #pragma unroll
    for (int q = 0; q < 4; q++)
        #pragma unroll
        for (int x = 0; x < 4; x++) accE[q][x] = 0.f;

    for (int c = 0; c < 4; c++) {
        const int hb = c * 128;
        __syncthreads();
        #pragma unroll
        for (int t = 0; t < 32; t++) {
            int lin = t * 256 + tid;          // sW2[hh][e]
            int hh = lin >> 6, e = lin & 63;
            sW[lin] = ew2[(size_t)(hb + hh) * EE + e];
        }
        __syncthreads();

        #pragma unroll 8
        for (int hh = 0; hh < 128; hh++) {
            float4 w = *(const float4*)&sW[hh * 64 + hc * 4];
            #pragma unroll
            for (int q = 0; q < 4; q++) {
                float a = sHe[(rg * 4 + q) * SHE_STRIDE + hb + hh];
                accE[q][0] += a * w.x; accE[q][1] += a * w.y;
                accE[q][2] += a * w.z; accE[q][3] += a * w.w;
            }
        }
    }

    // ---------------- residual + store ----------------
    float4 eb2v = __ldg((const float4*)&eb2[hc * 4]);
    #pragma unroll
    for (int q = 0; q < 4; q++) {
        int jl = rg * 4 + q;
        float4 ed = *(float4*)&sE[jl * 64 + hc * 4];
        float4 o = make_float4(ed.x + accE[q][0] + eb2v.x,
                               ed.y + accE[q][1] + eb2v.y,
                               ed.z + accE[q][2] + eb2v.z,
                               ed.w + accE[q][3] + eb2v.w);
        size_t base = ((size_t)((size_t)b * NN + i) * NN + (j0 + jl)) * EE + hc * 4;
        *(float4*)&out_edges[base] = o;
    }
}

// ============================================================
extern "C" void kernel_launch(void* const* d_in, const int* in_sizes, int n_in,
                              void* d_out, int out_size)
{
    const float* nodes = (const float*)d_in[0];
    const float* edges = (const float*)d_in[1];
    const float* adj   = (const float*)d_in[2];
    const float* nw1   = (const float*)d_in[3];
    const float* nb1   = (const float*)d_in[4];
    const float* ng    = (const float*)d_in[5];
    const float* nbt   = (const float*)d_in[6];
    const float* nw2   = (const float*)d_in[7];
    const float* nb2   = (const float*)d_in[8];
    const float* ew1   = (const float*)d_in[9];
    const float* eb1   = (const float*)d_in[10];
    const float* eg    = (const float*)d_in[11];
    const float* ebt   = (const float*)d_in[12];
    const float* ew2   = (const float*)d_in[13];
    const float* eb2   = (const float*)d_in[14];

    float* out_nodes = (float*)d_out;
    float* out_edges = out_nodes + (size_t)BB * NN * DD;

    cudaFuncSetAttribute(k_edge, cudaFuncAttributeMaxDynamicSharedMemorySize, EDGE_SMEM);

    k_agg <<<BB * NN, 256>>>(edges, adj);
    k_ninj<<<dim3(2, 48, 2), 256>>>(nodes, ew1, eb1);
    k_node<<<96, 256>>>(nodes, nw1, nb1, ng, nbt, nw2, nb2, out_nodes);
    k_edge<<<dim3(6, NN, BB), 256, EDGE_SMEM>>>(edges, ew1, eg, ebt, ew2, eb2, out_edges);
}